// round 1
// baseline (speedup 1.0000x reference)
#include <cuda_runtime.h>

#define NB 1024
#define QDIM 64
#define DDIM 512
#define EDIM 128
#define DCH 128
#define NCHUNK 4
#define NTHREADS 256
#define MSTRIDE 132

// shared memory layout (in floats)
#define AS_OFF 0
#define BS_OFF (QDIM*EDIM)                  /* 8192  */
#define IQN_OFF (BS_OFF + DCH*EDIM)        /* 24576 */
#define IDN_OFF (IQN_OFF + QDIM)           /* 24640 */
#define LF_OFF  (IDN_OFF + DCH)            /* 24768 */
#define FE_OFF  (LF_OFF + QDIM*22)         /* 26176 */
#define HID_OFF (FE_OFF + 24)              /* 26200 */
#define SMEM_FLOATS (HID_OFF + 16)         /* 26216 */
#define SMEM_BYTES (SMEM_FLOATS * 4)       /* 104864 */

__device__ float g_logits[2 * NB];

__device__ __forceinline__ float ex2f(float x) {
    float y;
    asm("ex2.approx.ftz.f32 %0, %1;" : "=f"(y) : "f"(x));
    return y;
}

__global__ void __launch_bounds__(NTHREADS, 2) knrm_main(
    const int* __restrict__ q1, const int* __restrict__ d1,
    const int* __restrict__ q2, const int* __restrict__ d2,
    const float* __restrict__ emb,
    const float* __restrict__ W0, const float* __restrict__ b0,
    const float* __restrict__ W1, const float* __restrict__ b1,
    const float* __restrict__ W2, const float* __restrict__ b2)
{
    extern __shared__ float sm[];
    const int b  = blockIdx.x;
    const int pr = blockIdx.y;
    const int* qi = pr ? q2 : q1;
    const int* di = pr ? d2 : d1;

    const int tid  = threadIdx.x;
    const int lane = tid & 31;
    const int warp = tid >> 5;

    float4* As4 = (float4*)(sm + AS_OFF);
    float4* Bs4 = (float4*)(sm + BS_OFF);
    float*  iqn = sm + IQN_OFF;
    float*  idn = sm + IDN_OFF;
    float*  lf  = sm + LF_OFF;
    float*  fe  = sm + FE_OFF;
    float*  hid = sm + HID_OFF;
    const float4* emb4 = (const float4*)emb;

    // ---------------- gather Q embeddings (swizzled) + query norms ----------------
    // warp w handles rows w*8 .. w*8+7 ; lane loads float4 #lane of the row (512B coalesced)
    #pragma unroll
    for (int r = 0; r < 8; r++) {
        int q   = warp * 8 + r;
        int idx = __ldg(&qi[b * QDIM + q]);
        float4 v = emb4[(size_t)idx * 32 + lane];
        As4[q * 32 + (lane ^ ((q >> 2) & 7))] = v;
        float s = fmaf(v.x, v.x, fmaf(v.y, v.y, fmaf(v.z, v.z, v.w * v.w)));
        #pragma unroll
        for (int o = 16; o; o >>= 1) s += __shfl_xor_sync(0xffffffffu, s, o);
        if (lane == 0) iqn[q] = (s > 0.f) ? rsqrtf(s) : 0.f;
    }
    __syncthreads();

    // GEMM thread mapping: 8 warps = 2(q) x 4(d); thread tile 4q x 8d
    const int wq = warp >> 2, wd = warp & 3;
    const int qg = lane >> 2, dg = lane & 3;
    const int q0 = wq * 32 + qg * 4;
    const int d0 = wd * 32 + dg * 8;
    // pooling mapping: thread = (pq, pg) -> q row pq, d-lane pg (stride 4)
    const int pq = tid >> 2, pg = tid & 3;

    float acc[21];
    #pragma unroll
    for (int j = 0; j < 21; j++) acc[j] = 0.f;

    // EXN[i] = exp(-i)
    const float EXN[10] = {
        1.f, 0.36787944117144233f, 0.1353352832366127f, 0.049787068367863944f,
        0.018315638888734179f, 0.006737946999085467f, 0.0024787521766663585f,
        0.0009118819655545162f, 0.00033546262790251185f, 0.00012340980408667956f };

    for (int ch = 0; ch < NCHUNK; ch++) {
        // ------------- gather D chunk (swizzled) + doc norms -------------
        #pragma unroll
        for (int r = 0; r < 16; r++) {
            int d   = warp * 16 + r;
            int idx = __ldg(&di[b * DDIM + ch * DCH + d]);
            float4 v = emb4[(size_t)idx * 32 + lane];
            Bs4[d * 32 + (lane ^ ((d >> 3) & 3))] = v;
            float s = fmaf(v.x, v.x, fmaf(v.y, v.y, fmaf(v.z, v.z, v.w * v.w)));
            #pragma unroll
            for (int o = 16; o; o >>= 1) s += __shfl_xor_sync(0xffffffffu, s, o);
            if (lane == 0) idn[d] = (s > 0.f) ? rsqrtf(s) : 0.f;
        }
        __syncthreads();

        // ------------- 64x128x128 FFMA GEMM (register tiled) -------------
        float c[4][8];
        #pragma unroll
        for (int i = 0; i < 4; i++)
            #pragma unroll
            for (int j = 0; j < 8; j++) c[i][j] = 0.f;

        #pragma unroll 4
        for (int kb = 0; kb < 32; kb++) {
            const int ks = kb ^ qg;
            float4 a0 = As4[(q0 + 0) * 32 + ks];
            float4 a1 = As4[(q0 + 1) * 32 + ks];
            float4 a2 = As4[(q0 + 2) * 32 + ks];
            float4 a3 = As4[(q0 + 3) * 32 + ks];
            const int kd = kb ^ dg;
            #pragma unroll
            for (int j = 0; j < 8; j++) {
                float4 bv = Bs4[(d0 + j) * 32 + kd];
                c[0][j] = fmaf(a0.x, bv.x, c[0][j]); c[0][j] = fmaf(a0.y, bv.y, c[0][j]);
                c[0][j] = fmaf(a0.z, bv.z, c[0][j]); c[0][j] = fmaf(a0.w, bv.w, c[0][j]);
                c[1][j] = fmaf(a1.x, bv.x, c[1][j]); c[1][j] = fmaf(a1.y, bv.y, c[1][j]);
                c[1][j] = fmaf(a1.z, bv.z, c[1][j]); c[1][j] = fmaf(a1.w, bv.w, c[1][j]);
                c[2][j] = fmaf(a2.x, bv.x, c[2][j]); c[2][j] = fmaf(a2.y, bv.y, c[2][j]);
                c[2][j] = fmaf(a2.z, bv.z, c[2][j]); c[2][j] = fmaf(a2.w, bv.w, c[2][j]);
                c[3][j] = fmaf(a3.x, bv.x, c[3][j]); c[3][j] = fmaf(a3.y, bv.y, c[3][j]);
                c[3][j] = fmaf(a3.z, bv.z, c[3][j]); c[3][j] = fmaf(a3.w, bv.w, c[3][j]);
            }
        }
        __syncthreads();   // everyone done reading Bs -> reuse as M tile

        // ------------- normalize & stage M tile -------------
        float* Ms = (float*)Bs4;   // [64][MSTRIDE]
        float idv[8];
        #pragma unroll
        for (int j = 0; j < 8; j++) idv[j] = idn[d0 + j];
        #pragma unroll
        for (int i = 0; i < 4; i++) {
            float qif = iqn[q0 + i];
            float4 m0, m1;
            m0.x = c[i][0] * qif * idv[0]; m0.y = c[i][1] * qif * idv[1];
            m0.z = c[i][2] * qif * idv[2]; m0.w = c[i][3] * qif * idv[3];
            m1.x = c[i][4] * qif * idv[4]; m1.y = c[i][5] * qif * idv[5];
            m1.z = c[i][6] * qif * idv[6]; m1.w = c[i][7] * qif * idv[7];
            *(float4*)&Ms[(q0 + i) * MSTRIDE + d0]     = m0;
            *(float4*)&Ms[(q0 + i) * MSTRIDE + d0 + 4] = m1;
        }
        __syncthreads();

        // ------------- Gaussian kernel pooling (ratio-chain, 4 MUFU/elem) -------------
        #pragma unroll 2
        for (int it = 0; it < 32; it++) {
            float u  = Ms[pq * MSTRIDE + pg + it * 4];
            float a  = ex2f(u *  14.426950408889634f);   // exp(10u)
            float ia = ex2f(u * -14.426950408889634f);   // exp(-10u)
            float t  = u - 0.05f;
            float k0 = ex2f(t * t * -72.13475204444819f); // exp(-50 t^2), anchor j=10
            acc[10] += k0;
            float kk = k0;
            #pragma unroll
            for (int s2 = 0; s2 < 9; s2++) {   // j = 11 .. 19
                kk *= a; kk *= EXN[s2 + 1];
                acc[11 + s2] += kk;
            }
            kk = k0;
            #pragma unroll
            for (int s2 = 0; s2 < 10; s2++) {  // j = 9 .. 0
                kk *= ia; kk *= EXN[s2];
                acc[9 - s2] += kk;
            }
            float te = u - 1.0f;               // exact kernel (sigma=1e-3)
            acc[20] += ex2f(te * te * -721347.5204444817f);
        }
        __syncthreads();   // before next gather overwrites Bs
    }

    // ------------- reduce across the 4 d-lanes, log1p, reduce over q -------------
    #pragma unroll
    for (int j = 0; j < 21; j++) {
        acc[j] += __shfl_xor_sync(0xffffffffu, acc[j], 1);
        acc[j] += __shfl_xor_sync(0xffffffffu, acc[j], 2);
    }
    if (pg == 0) {
        #pragma unroll
        for (int j = 0; j < 21; j++) lf[pq * 22 + j] = log1pf(acc[j]);
    }
    __syncthreads();
    if (tid < 21) {
        float s = 0.f;
        for (int q = 0; q < QDIM; q++) s += lf[q * 22 + tid];
        fe[tid] = s;
    }
    __syncthreads();

    // ------------- tiny MLP (warp 0) -------------
    if (warp == 0) {
        if (lane < 10) {
            float s = __ldg(&b0[lane]);
            #pragma unroll
            for (int j = 0; j < 21; j++) s = fmaf(fe[j], __ldg(&W0[lane * 21 + j]), s);
            hid[lane] = fmaxf(s, 0.f);
        }
        __syncwarp();
        if (lane < 5) {
            float s = __ldg(&b1[lane]);
            #pragma unroll
            for (int j = 0; j < 10; j++) s = fmaf(hid[j], __ldg(&W1[lane * 10 + j]), s);
            hid[10 + lane] = fmaxf(s, 0.f);
        }
        __syncwarp();
        if (lane == 0) {
            float s = __ldg(&b2[0]);
            #pragma unroll
            for (int j = 0; j < 5; j++) s = fmaf(hid[10 + j], __ldg(&W2[j]), s);
            g_logits[pr * NB + b] = s;
        }
    }
}

__global__ void knrm_final(float* __restrict__ out)
{
    int i = blockIdx.x * blockDim.x + threadIdx.x;
    if (i < NB) {
        float z = g_logits[NB + i] - g_logits[i];   // -(l1 - l2)
        out[i] = 1.0f / (1.0f + expf(z));
    }
}

extern "C" void kernel_launch(void* const* d_in, const int* in_sizes, int n_in,
                              void* d_out, int out_size)
{
    const int*   q1  = (const int*)d_in[0];
    const int*   d1  = (const int*)d_in[1];
    const int*   q2  = (const int*)d_in[2];
    const int*   d2  = (const int*)d_in[3];
    const float* emb = (const float*)d_in[4];
    const float* W0  = (const float*)d_in[5];
    const float* b0  = (const float*)d_in[6];
    const float* W1  = (const float*)d_in[7];
    const float* b1  = (const float*)d_in[8];
    const float* W2  = (const float*)d_in[9];
    const float* b2  = (const float*)d_in[10];

    cudaFuncSetAttribute(knrm_main, cudaFuncAttributeMaxDynamicSharedMemorySize, SMEM_BYTES);

    dim3 grid(NB, 2);
    knrm_main<<<grid, NTHREADS, SMEM_BYTES>>>(q1, d1, q2, d2, emb,
                                              W0, b0, W1, b1, W2, b2);
    knrm_final<<<NB / 256, 256>>>((float*)d_out);
}

// round 2
// speedup vs baseline: 1.9390x; 1.9390x over previous
#include <cuda_runtime.h>
#include <cstdint>

#define NB 1024
#define QDIM 64
#define DDIM 512
#define EDIM 128
#define DCH 128
#define NCHUNK 4
#define NTHREADS 256
#define RSTRIDE 132              /* padded row stride in floats (33 float4) */

// shared memory layout (float offsets)
#define AS_OFF   0                               /* 64*132  = 8448  */
#define BS_OFF   (AS_OFF + QDIM*RSTRIDE)         /* 128*132 = 16896 */
#define IQN_OFF  (BS_OFF + DCH*RSTRIDE)          /* 64  */
#define IDN_OFF  (IQN_OFF + QDIM)                /* 128 */
#define QID_OFF  (IDN_OFF + DCH)                 /* 64  */
#define DID_OFF  (QID_OFF + QDIM)                /* 128 */
#define LF_OFF   (DID_OFF + DCH)                 /* 64*22 = 1408 */
#define FE_OFF   (LF_OFF + QDIM*22)              /* 24 */
#define HID_OFF  (FE_OFF + 24)                   /* 16 */
#define SMEM_FLOATS (HID_OFF + 16)
#define SMEM_BYTES  (SMEM_FLOATS * 4)            /* 108,704 B */

__device__ float g_logits[2 * NB];

__device__ __forceinline__ float ex2f(float x) {
    float y;
    asm("ex2.approx.ftz.f32 %0, %1;" : "=f"(y) : "f"(x));
    return y;
}

__device__ __forceinline__ uint32_t tf32r(float x) {
    uint32_t y;
    asm("cvt.rna.tf32.f32 %0, %1;" : "=r"(y) : "f"(x));
    return y;
}

__device__ __forceinline__ void mma_tf32(float c[4], const uint32_t a[4],
                                         uint32_t b0, uint32_t b1) {
    asm volatile(
        "mma.sync.aligned.m16n8k8.row.col.f32.tf32.tf32.f32 "
        "{%0,%1,%2,%3}, {%4,%5,%6,%7}, {%8,%9}, {%0,%1,%2,%3};"
        : "+f"(c[0]), "+f"(c[1]), "+f"(c[2]), "+f"(c[3])
        : "r"(a[0]), "r"(a[1]), "r"(a[2]), "r"(a[3]), "r"(b0), "r"(b1));
}

__global__ void __launch_bounds__(NTHREADS, 2) knrm_main(
    const int* __restrict__ q1, const int* __restrict__ d1,
    const int* __restrict__ q2, const int* __restrict__ d2,
    const float* __restrict__ emb,
    const float* __restrict__ W0, const float* __restrict__ b0,
    const float* __restrict__ W1, const float* __restrict__ b1,
    const float* __restrict__ W2, const float* __restrict__ b2)
{
    extern __shared__ float sm[];
    const int b  = blockIdx.x;
    const int pr = blockIdx.y;
    const int* qi = pr ? q2 : q1;
    const int* di = pr ? d2 : d1;

    const int tid  = threadIdx.x;
    const int lane = tid & 31;
    const int warp = tid >> 5;
    const int g    = lane >> 2;      // mma groupID
    const int t4   = lane & 3;       // mma threadID-in-group

    float4* As4 = (float4*)(sm + AS_OFF);
    float4* Bs4 = (float4*)(sm + BS_OFF);
    float*  Af  = sm + AS_OFF;
    float*  Bf  = sm + BS_OFF;
    float*  iqn = sm + IQN_OFF;
    float*  idn = sm + IDN_OFF;
    int*    qids = (int*)(sm + QID_OFF);
    int*    dids = (int*)(sm + DID_OFF);
    float*  lf  = sm + LF_OFF;
    float*  fe  = sm + FE_OFF;
    float*  hid = sm + HID_OFF;
    const float4* emb4 = (const float4*)emb;

    // ---------------- gather Q embeddings (stride-132) + norms + ids ----------------
    #pragma unroll
    for (int r = 0; r < 8; r++) {
        int q   = warp * 8 + r;
        int idx = __ldg(&qi[b * QDIM + q]);
        float4 v = emb4[(size_t)idx * 32 + lane];
        float s = fmaf(v.x, v.x, fmaf(v.y, v.y, fmaf(v.z, v.z, v.w * v.w)));
        #pragma unroll
        for (int o = 16; o; o >>= 1) s += __shfl_xor_sync(0xffffffffu, s, o);
        float4 vt;
        vt.x = __uint_as_float(tf32r(v.x)); vt.y = __uint_as_float(tf32r(v.y));
        vt.z = __uint_as_float(tf32r(v.z)); vt.w = __uint_as_float(tf32r(v.w));
        As4[q * 33 + lane] = vt;
        if (lane == 0) {
            iqn[q]  = (s > 0.f) ? rsqrtf(s) : 0.f;
            qids[q] = idx;
        }
    }
    __syncthreads();

    // warp tiling for GEMM: 2 (q) x 4 (d) warps, warp tile 32q x 32d
    const int wq = warp >> 2, wd = warp & 3;
    const int q0w = wq * 32;
    const int d0w = wd * 32;
    // pooling mapping
    const int pq = tid >> 2, pg = tid & 3;
    const int qid_my = qids[pq];
    const int qsent  = (qid_my == 0) ? -1 : qid_my;

    float acc[21];
    #pragma unroll
    for (int j = 0; j < 21; j++) acc[j] = 0.f;

    for (int ch = 0; ch < NCHUNK; ch++) {
        // ------------- gather D chunk + norms + ids -------------
        #pragma unroll
        for (int r = 0; r < 16; r++) {
            int d   = warp * 16 + r;
            int idx = __ldg(&di[b * DDIM + ch * DCH + d]);
            float4 v = emb4[(size_t)idx * 32 + lane];
            float s = fmaf(v.x, v.x, fmaf(v.y, v.y, fmaf(v.z, v.z, v.w * v.w)));
            #pragma unroll
            for (int o = 16; o; o >>= 1) s += __shfl_xor_sync(0xffffffffu, s, o);
            float4 vt;
            vt.x = __uint_as_float(tf32r(v.x)); vt.y = __uint_as_float(tf32r(v.y));
            vt.z = __uint_as_float(tf32r(v.z)); vt.w = __uint_as_float(tf32r(v.w));
            Bs4[d * 33 + lane] = vt;
            if (lane == 0) {
                idn[d]  = (s > 0.f) ? rsqrtf(s) : 0.f;
                dids[d] = idx;
            }
        }
        __syncthreads();

        // ------------- 64x128x128 tf32 tensor-core GEMM -------------
        float c[2][4][4];
        #pragma unroll
        for (int i = 0; i < 2; i++)
            #pragma unroll
            for (int j = 0; j < 4; j++)
                #pragma unroll
                for (int r = 0; r < 4; r++) c[i][j][r] = 0.f;

        const int abase = (q0w + g) * RSTRIDE + t4;
        const int bbase = (d0w + g) * RSTRIDE + t4;

        #pragma unroll
        for (int ks = 0; ks < 16; ks++) {
            const int k0 = ks * 8;
            uint32_t a[2][4];
            #pragma unroll
            for (int i = 0; i < 2; i++) {
                const float* p = Af + abase + i * (16 * RSTRIDE) + k0;
                a[i][0] = __float_as_uint(p[0]);
                a[i][1] = __float_as_uint(p[8 * RSTRIDE]);
                a[i][2] = __float_as_uint(p[4]);
                a[i][3] = __float_as_uint(p[8 * RSTRIDE + 4]);
            }
            #pragma unroll
            for (int j = 0; j < 4; j++) {
                const float* p = Bf + bbase + j * (8 * RSTRIDE) + k0;
                uint32_t bb0 = __float_as_uint(p[0]);
                uint32_t bb1 = __float_as_uint(p[4]);
                mma_tf32(c[0][j], a[0], bb0, bb1);
                mma_tf32(c[1][j], a[1], bb0, bb1);
            }
        }
        __syncthreads();   // all warps done reading Bs -> reuse as M tile

        // ------------- normalize & stage M tile (reuse Bs region) -------------
        float* Ms = Bf;    // [64][RSTRIDE]
        #pragma unroll
        for (int i = 0; i < 2; i++) {
            int r0 = q0w + 16 * i + g;
            float iq0 = iqn[r0], iq1 = iqn[r0 + 8];
            #pragma unroll
            for (int j = 0; j < 4; j++) {
                int col = d0w + 8 * j + 2 * t4;
                float id0 = idn[col], id1 = idn[col + 1];
                float2 m0, m1;
                m0.x = c[i][j][0] * iq0 * id0;  m0.y = c[i][j][1] * iq0 * id1;
                m1.x = c[i][j][2] * iq1 * id0;  m1.y = c[i][j][3] * iq1 * id1;
                *(float2*)&Ms[r0 * RSTRIDE + col]       = m0;
                *(float2*)&Ms[(r0 + 8) * RSTRIDE + col] = m1;
            }
        }
        __syncthreads();

        // ------------- Gaussian pooling: ratio chain, deferred scaling -------------
        #pragma unroll 4
        for (int it = 0; it < 32; it++) {
            float u   = Ms[pq * RSTRIDE + pg + it * 4];
            int   did = dids[pg + it * 4];
            float z   = ex2f(u *  14.426950408889634f);   // exp(10u)
            float iz  = ex2f(u * -14.426950408889634f);   // exp(-10u)
            float t0  = u - 0.05f;
            float k0  = ex2f(t0 * t0 * -72.13475204444819f); // anchor j=10
            acc[10] += k0;
            float tt = k0;
            tt *= z;  acc[11] += tt;  tt *= z;  acc[12] += tt;
            tt *= z;  acc[13] += tt;  tt *= z;  acc[14] += tt;
            tt *= z;  acc[15] += tt;  tt *= z;  acc[16] += tt;
            tt *= z;  acc[17] += tt;  tt *= z;  acc[18] += tt;
            tt *= z;  acc[19] += tt;
            tt = k0;
            tt *= iz; acc[9]  += tt;  tt *= iz; acc[8]  += tt;
            tt *= iz; acc[7]  += tt;  tt *= iz; acc[6]  += tt;
            tt *= iz; acc[5]  += tt;  tt *= iz; acc[4]  += tt;
            tt *= iz; acc[3]  += tt;  tt *= iz; acc[2]  += tt;
            tt *= iz; acc[1]  += tt;  tt *= iz; acc[0]  += tt;
            if (did == qsent) acc[20] += 1.0f;   // exact-match kernel (sigma=1e-3)
        }
        __syncthreads();   // before next gather overwrites Bs
    }

    // deferred chain scaling: k_j = k0 * z^m * exp(-m(m+1)/2), m = j-10
    {
        const float E1  = 0.36787944117144233f;     // e^-1
        const float E3  = 0.049787068367863944f;    // e^-3
        const float E6  = 0.0024787521766663585f;   // e^-6
        const float E10 = 4.5399929762484854e-05f;  // e^-10
        const float E15 = 3.059023205018258e-07f;   // e^-15
        const float E21 = 7.582560427911907e-10f;   // e^-21
        const float E28 = 6.914400106940203e-13f;   // e^-28
        const float E36 = 2.319522830243569e-16f;   // e^-36
        const float E45 = 2.8625185805493937e-20f;  // e^-45
        acc[11] *= E1;  acc[12] *= E3;  acc[13] *= E6;  acc[14] *= E10;
        acc[15] *= E15; acc[16] *= E21; acc[17] *= E28; acc[18] *= E36;
        acc[19] *= E45;
        acc[8]  *= E1;  acc[7]  *= E3;  acc[6]  *= E6;  acc[5]  *= E10;
        acc[4]  *= E15; acc[3]  *= E21; acc[2]  *= E28; acc[1]  *= E36;
        acc[0]  *= E45;
    }

    // reduce across the 4 d-lanes, log1p, reduce over q
    #pragma unroll
    for (int j = 0; j < 21; j++) {
        acc[j] += __shfl_xor_sync(0xffffffffu, acc[j], 1);
        acc[j] += __shfl_xor_sync(0xffffffffu, acc[j], 2);
    }
    if (pg == 0) {
        #pragma unroll
        for (int j = 0; j < 21; j++) lf[pq * 22 + j] = log1pf(acc[j]);
    }
    __syncthreads();
    if (tid < 21) {
        float s = 0.f;
        for (int q = 0; q < QDIM; q++) s += lf[q * 22 + tid];
        fe[tid] = s;
    }
    __syncthreads();

    // tiny MLP (warp 0)
    if (warp == 0) {
        if (lane < 10) {
            float s = __ldg(&b0[lane]);
            #pragma unroll
            for (int j = 0; j < 21; j++) s = fmaf(fe[j], __ldg(&W0[lane * 21 + j]), s);
            hid[lane] = fmaxf(s, 0.f);
        }
        __syncwarp();
        if (lane < 5) {
            float s = __ldg(&b1[lane]);
            #pragma unroll
            for (int j = 0; j < 10; j++) s = fmaf(hid[j], __ldg(&W1[lane * 10 + j]), s);
            hid[10 + lane] = fmaxf(s, 0.f);
        }
        __syncwarp();
        if (lane == 0) {
            float s = __ldg(&b2[0]);
            #pragma unroll
            for (int j = 0; j < 5; j++) s = fmaf(hid[10 + j], __ldg(&W2[j]), s);
            g_logits[pr * NB + b] = s;
        }
    }
}

__global__ void knrm_final(float* __restrict__ out)
{
    int i = blockIdx.x * blockDim.x + threadIdx.x;
    if (i < NB) {
        float z = g_logits[NB + i] - g_logits[i];   // -(l1 - l2)
        out[i] = 1.0f / (1.0f + expf(z));
    }
}

extern "C" void kernel_launch(void* const* d_in, const int* in_sizes, int n_in,
                              void* d_out, int out_size)
{
    const int*   q1  = (const int*)d_in[0];
    const int*   d1  = (const int*)d_in[1];
    const int*   q2  = (const int*)d_in[2];
    const int*   d2  = (const int*)d_in[3];
    const float* emb = (const float*)d_in[4];
    const float* W0  = (const float*)d_in[5];
    const float* b0  = (const float*)d_in[6];
    const float* W1  = (const float*)d_in[7];
    const float* b1  = (const float*)d_in[8];
    const float* W2  = (const float*)d_in[9];
    const float* b2  = (const float*)d_in[10];

    cudaFuncSetAttribute(knrm_main, cudaFuncAttributeMaxDynamicSharedMemorySize, SMEM_BYTES);

    dim3 grid(NB, 2);
    knrm_main<<<grid, NTHREADS, SMEM_BYTES>>>(q1, d1, q2, d2, emb,
                                              W0, b0, W1, b1, W2, b2);
    knrm_final<<<NB / 256, 256>>>((float*)d_out);
}

// round 5
// speedup vs baseline: 2.5458x; 1.3130x over previous
#include <cuda_runtime.h>
#include <cuda_fp16.h>
#include <cstdint>

#define NB 1024
#define QDIM 64
#define DDIM 512
#define EDIM 128
#define DCH 128
#define NCHUNK 4
#define NTHREADS 256

#define AROWB 272                 /* bytes per fp16 tile row: 128*2 + 16 pad */
#define MST 136                   /* Ms row stride in floats: 136%32==8 -> conflict-free */

// shared memory float-index layout
#define AS_F   0                  /* queries fp16 tile: 64 rows * 68 floats = 4352 */
#define BS_F   4352               /* docs    fp16 tile: 128 rows * 68 floats = 8704 */
#define MS_F   13056              /* M tile [64][136] floats = 8704 */
#define LF_F   MS_F               /* per-q log1p feats alias Ms after the loop */
#define QID_F  21760              /* 64 ints */
#define DID_F  21824              /* 2 x 128 ints (double buffered) */
#define FE_F   22080              /* 24 */
#define HID_F  22104              /* 16 */
#define SMEM_FLOATS 22120
#define SMEM_BYTES (SMEM_FLOATS * 4)   /* 88,480 B -> 2 CTAs/SM */

__device__ float g_logits[2 * NB];

__device__ __forceinline__ float ex2f(float x) {
    float y; asm("ex2.approx.ftz.f32 %0, %1;" : "=f"(y) : "f"(x)); return y;
}

__device__ __forceinline__ uint32_t h2u(__half2 h) {
    union { __half2 h; uint32_t u; } c; c.h = h; return c.u;
}

__device__ __forceinline__ void mma_fp16(float c[4], const uint32_t a[4],
                                         uint32_t b0, uint32_t b1) {
    asm volatile(
        "mma.sync.aligned.m16n8k16.row.col.f32.f16.f16.f32 "
        "{%0,%1,%2,%3}, {%4,%5,%6,%7}, {%8,%9}, {%0,%1,%2,%3};"
        : "+f"(c[0]), "+f"(c[1]), "+f"(c[2]), "+f"(c[3])
        : "r"(a[0]), "r"(a[1]), "r"(a[2]), "r"(a[3]), "r"(b0), "r"(b1));
}

__global__ void __launch_bounds__(NTHREADS, 2) knrm_main(
    const int* __restrict__ q1, const int* __restrict__ d1,
    const int* __restrict__ q2, const int* __restrict__ d2,
    const float* __restrict__ emb,
    const float* __restrict__ W0, const float* __restrict__ b0,
    const float* __restrict__ W1, const float* __restrict__ b1,
    const float* __restrict__ W2, const float* __restrict__ b2)
{
    extern __shared__ float sm[];
    const int b  = blockIdx.x;
    const int pr = blockIdx.y;
    const int* qi = pr ? q2 : q1;
    const int* di = pr ? d2 : d1;

    const int tid  = threadIdx.x;
    const int lane = tid & 31;
    const int warp = tid >> 5;
    const int g    = lane >> 2;      // mma groupID (row within fragment)
    const int t    = lane & 3;       // mma threadID-in-group

    char*  smc  = (char*)sm;
    float* Ms   = sm + MS_F;
    int*   qids = (int*)(sm + QID_F);
    int*   dids = (int*)(sm + DID_F);
    float* lf   = sm + LF_F;
    float* fe   = sm + FE_F;
    float* hid  = sm + HID_F;
    const float4* emb4 = (const float4*)emb;

    // ---------------- gather queries: prescale by inv-norm -> fp16 tile ----------------
    #pragma unroll
    for (int r = 0; r < 8; r++) {
        int q   = warp * 8 + r;
        int idx = __ldg(&qi[b * QDIM + q]);
        float4 v = emb4[(size_t)idx * 32 + lane];
        float s = fmaf(v.x, v.x, fmaf(v.y, v.y, fmaf(v.z, v.z, v.w * v.w)));
        #pragma unroll
        for (int o = 16; o; o >>= 1) s += __shfl_xor_sync(0xffffffffu, s, o);
        float sc = (s > 0.f) ? rsqrtf(s) : 0.f;
        uint2 pk = make_uint2(h2u(__floats2half2_rn(v.x * sc, v.y * sc)),
                              h2u(__floats2half2_rn(v.z * sc, v.w * sc)));
        *(uint2*)(smc + AS_F * 4 + q * AROWB + lane * 8) = pk;
        if (lane == 0) qids[q] = idx;
    }

    // warp tiling: 2(q) x 4(d) warps, warp tile 32q x 32d
    const int q0w = (warp >> 2) * 32;
    const int d0w = (warp & 3) * 32;
    // pooling mapping: thread -> q row pq, 2-wide d-lane t
    const int pq = tid >> 2;

    float acc[21];
    #pragma unroll
    for (int j = 0; j < 21; j++) acc[j] = 0.f;

    const uint32_t abase = (uint32_t)(AS_F * 4 + (q0w + g) * AROWB + 4 * t);
    const uint32_t bbase = (uint32_t)(BS_F * 4 + (d0w + g) * AROWB + 4 * t);

    int qid_my, qsent = -2;   // set after first sync (qids needs visibility)

    for (int ch = 0; ch < NCHUNK; ch++) {
        // ------------- gather doc chunk (prescaled fp16) + ids (double buffered) -------------
        int* didc = dids + (ch & 1) * DCH;
        #pragma unroll
        for (int i = 0; i < 16; i++) {
            int d   = warp * 16 + i;
            int idx = __ldg(&di[b * DDIM + ch * DCH + d]);
            float4 v = emb4[(size_t)idx * 32 + lane];
            float s = fmaf(v.x, v.x, fmaf(v.y, v.y, fmaf(v.z, v.z, v.w * v.w)));
            #pragma unroll
            for (int o = 16; o; o >>= 1) s += __shfl_xor_sync(0xffffffffu, s, o);
            float sc = (s > 0.f) ? rsqrtf(s) : 0.f;
            uint2 pk = make_uint2(h2u(__floats2half2_rn(v.x * sc, v.y * sc)),
                                  h2u(__floats2half2_rn(v.z * sc, v.w * sc)));
            *(uint2*)(smc + BS_F * 4 + d * AROWB + lane * 8) = pk;
            if (lane == 0) didc[d] = idx;
        }
        __syncthreads();
        if (qsent == -2) { qid_my = qids[pq]; qsent = (qid_my == 0) ? -1 : qid_my; }

        // ------------- 64x128x128 fp16 m16n8k16 GEMM -------------
        float c[2][4][4];
        #pragma unroll
        for (int i = 0; i < 2; i++)
            #pragma unroll
            for (int j = 0; j < 4; j++)
                #pragma unroll
                for (int r = 0; r < 4; r++) c[i][j][r] = 0.f;

        #pragma unroll
        for (int ks = 0; ks < 8; ks++) {
            const uint32_t ko = 32u * ks;
            uint32_t a[2][4];
            #pragma unroll
            for (int i = 0; i < 2; i++) {
                const char* p = smc + abase + i * (16 * AROWB) + ko;
                a[i][0] = *(const uint32_t*)(p);
                a[i][1] = *(const uint32_t*)(p + 8 * AROWB);
                a[i][2] = *(const uint32_t*)(p + 16);
                a[i][3] = *(const uint32_t*)(p + 8 * AROWB + 16);
            }
            #pragma unroll
            for (int j = 0; j < 4; j++) {
                const char* p = smc + bbase + j * (8 * AROWB) + ko;
                uint32_t bb0 = *(const uint32_t*)(p);
                uint32_t bb1 = *(const uint32_t*)(p + 16);
                mma_fp16(c[0][j], a[0], bb0, bb1);
                mma_fp16(c[1][j], a[1], bb0, bb1);
            }
        }

        // ------------- stage M tile (cosines, already normalized) -------------
        #pragma unroll
        for (int i = 0; i < 2; i++) {
            int r0 = q0w + 16 * i + g;
            #pragma unroll
            for (int j = 0; j < 4; j++) {
                int col = d0w + 8 * j + 2 * t;
                *(float2*)&Ms[r0 * MST + col]       = make_float2(c[i][j][0], c[i][j][1]);
                *(float2*)&Ms[(r0 + 8) * MST + col] = make_float2(c[i][j][2], c[i][j][3]);
            }
        }
        __syncthreads();   // Ms complete; also: all B reads done -> next gather may write B

        // ------------- Gaussian pooling: ratio chain + deferred scaling, float2 -------------
        #pragma unroll 2
        for (int it = 0; it < 16; it++) {
            float2 uu = *(const float2*)&Ms[pq * MST + 2 * t + 8 * it];
            int2   dd = *(const int2*)&didc[2 * t + 8 * it];
            #pragma unroll
            for (int e = 0; e < 2; e++) {
                float u   = e ? uu.y : uu.x;
                int   did = e ? dd.y : dd.x;
                float z   = ex2f(u *  14.426950408889634f);   // exp(10u)
                float iz  = ex2f(u * -14.426950408889634f);   // exp(-10u)
                float t0  = u - 0.05f;
                float k0  = ex2f(t0 * t0 * -72.13475204444819f); // anchor j=10
                acc[10] += k0;
                float tt = k0;
                tt *= z;  acc[11] += tt;  tt *= z;  acc[12] += tt;
                tt *= z;  acc[13] += tt;  tt *= z;  acc[14] += tt;
                tt *= z;  acc[15] += tt;  tt *= z;  acc[16] += tt;
                tt *= z;  acc[17] += tt;  tt *= z;  acc[18] += tt;
                tt *= z;  acc[19] += tt;
                tt = k0;
                tt *= iz; acc[9]  += tt;  tt *= iz; acc[8]  += tt;
                tt *= iz; acc[7]  += tt;  tt *= iz; acc[6]  += tt;
                tt *= iz; acc[5]  += tt;  tt *= iz; acc[4]  += tt;
                tt *= iz; acc[3]  += tt;  tt *= iz; acc[2]  += tt;
                tt *= iz; acc[1]  += tt;  tt *= iz; acc[0]  += tt;
                if (did == qsent) acc[20] += 1.0f;   // exact-match kernel (sigma=1e-3)
            }
        }
        // no sync: pooling reads Ms/didc[ch]; next gather writes Bs/didc[ch^1]
    }

    // deferred chain scaling: k_j = k0 * z^m * exp(-m(m+1)/2)
    {
        const float E1  = 0.36787944117144233f,   E3  = 0.049787068367863944f;
        const float E6  = 0.0024787521766663585f, E10 = 4.5399929762484854e-05f;
        const float E15 = 3.059023205018258e-07f, E21 = 7.582560427911907e-10f;
        const float E28 = 6.914400106940203e-13f, E36 = 2.319522830243569e-16f;
        const float E45 = 2.8625185805493937e-20f;
        acc[11] *= E1;  acc[12] *= E3;  acc[13] *= E6;  acc[14] *= E10;
        acc[15] *= E15; acc[16] *= E21; acc[17] *= E28; acc[18] *= E36; acc[19] *= E45;
        acc[8]  *= E1;  acc[7]  *= E3;  acc[6]  *= E6;  acc[5]  *= E10;
        acc[4]  *= E15; acc[3]  *= E21; acc[2]  *= E28; acc[1]  *= E36; acc[0]  *= E45;
    }

    // reduce across the 4 d-lanes, log1p per q, reduce over q
    #pragma unroll
    for (int j = 0; j < 21; j++) {
        acc[j] += __shfl_xor_sync(0xffffffffu, acc[j], 1);
        acc[j] += __shfl_xor_sync(0xffffffffu, acc[j], 2);
    }
    __syncthreads();           // all pooling reads of Ms done; lf aliases Ms
    if ((tid & 3) == 0) {
        #pragma unroll
        for (int j = 0; j < 21; j++) lf[pq * 22 + j] = log1pf(acc[j]);
    }
    __syncthreads();
    if (tid < 21) {
        float s = 0.f;
        for (int q = 0; q < QDIM; q++) s += lf[q * 22 + tid];
        fe[tid] = s;
    }
    __syncthreads();

    // tiny MLP (warp 0)
    if (warp == 0) {
        if (lane < 10) {
            float s = __ldg(&b0[lane]);
            #pragma unroll
            for (int j = 0; j < 21; j++) s = fmaf(fe[j], __ldg(&W0[lane * 21 + j]), s);
            hid[lane] = fmaxf(s, 0.f);
        }
        __syncwarp();
        if (lane < 5) {
            float s = __ldg(&b1[lane]);
            #pragma unroll
            for (int j = 0; j < 10; j++) s = fmaf(hid[j], __ldg(&W1[lane * 10 + j]), s);
            hid[10 + lane] = fmaxf(s, 0.f);
        }
        __syncwarp();
        if (lane == 0) {
            float s = __ldg(&b2[0]);
            #pragma unroll
            for (int j = 0; j < 5; j++) s = fmaf(hid[10 + j], __ldg(&W2[j]), s);
            g_logits[pr * NB + b] = s;
        }
    }
}

__global__ void knrm_final(float* __restrict__ out)
{
    int i = blockIdx.x * blockDim.x + threadIdx.x;
    if (i < NB) {
        float z = g_logits[NB + i] - g_logits[i];   // -(l1 - l2)
        out[i] = 1.0f / (1.0f + expf(z));
    }
}

extern "C" void kernel_launch(void* const* d_in, const int* in_sizes, int n_in,
                              void* d_out, int out_size)
{
    const int*   q1  = (const int*)d_in[0];
    const int*   d1  = (const int*)d_in[1];
    const int*   q2  = (const int*)d_in[2];
    const int*   d2  = (const int*)d_in[3];
    const float* emb = (const float*)d_in[4];
    const float* W0  = (const float*)d_in[5];
    const float* b0  = (const float*)d_in[6];
    const float* W1  = (const float*)d_in[7];
    const float* b1  = (const float*)d_in[8];
    const float* W2  = (const float*)d_in[9];
    const float* b2  = (const float*)d_in[10];

    cudaFuncSetAttribute(knrm_main, cudaFuncAttributeMaxDynamicSharedMemorySize, SMEM_BYTES);

    dim3 grid(NB, 2);
    knrm_main<<<grid, NTHREADS, SMEM_BYTES>>>(q1, d1, q2, d2, emb,
                                              W0, b0, W1, b1, W2, b2);
    knrm_final<<<NB / 256, 256>>>((float*)d_out);
}